// round 15
// baseline (speedup 1.0000x reference)
#include <cuda_runtime.h>

// Sparse attention: query l attends to keys l-d, d in
//   {0,1,2,3,4,5,6,7,9,13,21,37,69,133,261,517,1029} (clipped at 0).
// B=4, L=2048, H=8, E=D=64. Layouts [B,L,H,E].
// v8: 4 queries/warp. Each 16-lane half handles two ADJACENT queries (l,l+1)
//     whose 8-row windows share a 9-row union held once in registers, so one
//     window LDG feeds both queries' dot products. 58 LSU ops / 4 queries
//     (vs 76 in v5). Reduction/softmax identical to validated v5, per query.

namespace {
constexpr int Lq = 2048;
constexpr int Hh = 8;
constexpr int Ee = 64;
}

__device__ __forceinline__ float dot4(const float4 a, const float4 b)
{
    float t = a.x * b.x;
    t = fmaf(a.y, b.y, t);
    t = fmaf(a.z, b.z, t);
    return fmaf(a.w, b.w, t);
}

// v5's halving tree over the 16-lane group: p[8] partial scores ->
// half-sum of score (lane16 & 7), to be merged with the log half via mask 8.
__device__ __forceinline__ float tree8(float p[8], const int lane16)
{
    const unsigned FULL = 0xffffffffu;
    const bool b2 = lane16 & 4;
#pragma unroll
    for (int i = 0; i < 4; ++i) {
        const float send = b2 ? p[i] : p[i + 4];
        const float r    = __shfl_xor_sync(FULL, send, 4);
        p[i] = (b2 ? p[i + 4] : p[i]) + r;
    }
    const bool b1 = lane16 & 2;
#pragma unroll
    for (int i = 0; i < 2; ++i) {
        const float send = b1 ? p[i] : p[i + 2];
        const float r    = __shfl_xor_sync(FULL, send, 2);
        p[i] = (b1 ? p[i + 2] : p[i]) + r;
    }
    const bool b0 = lane16 & 1;
    const float send = b0 ? p[0] : p[1];
    const float r    = __shfl_xor_sync(FULL, send, 1);
    return (b0 ? p[1] : p[0]) + r;
}

// K log phase for one query: 8 log rows + the 1029 row, 5+4 batches.
__device__ __forceinline__ void klog(const float4* __restrict__ kbase, const int rs4,
                                     const int l, const float4 q, const int lane16,
                                     float& bout, float& s16)
{
    const int offsB[8] = {9,13,21,37,69,133,261,517};
    float p[8];
    {
        float4 kb[5];
#pragma unroll
        for (int j = 0; j < 5; ++j) {
            int k = l - offsB[j]; k = k >= 0 ? k : 0;
            kb[j] = kbase[k * rs4];
        }
#pragma unroll
        for (int j = 0; j < 5; ++j) p[j] = dot4(q, kb[j]);
    }
    {
        float4 kb[4];
#pragma unroll
        for (int j = 0; j < 3; ++j) {
            int k = l - offsB[5 + j]; k = k >= 0 ? k : 0;
            kb[j] = kbase[k * rs4];
        }
        { int k = l - 1029; k = k >= 0 ? k : 0; kb[3] = kbase[k * rs4]; }
#pragma unroll
        for (int j = 0; j < 3; ++j) p[5 + j] = dot4(q, kb[j]);
        s16 = dot4(q, kb[3]);
    }
#pragma unroll
    for (int m = 8; m; m >>= 1)
        s16 += __shfl_xor_sync(0xffffffffu, s16, m);
    bout = tree8(p, lane16);
}

// V log phase for one query: accumulate 8 log rows + the 1029 row.
__device__ __forceinline__ void vlog(const float4* __restrict__ vbase, const int rs4,
                                     const int l, const float w, const float w16,
                                     float4& acc)
{
    const int offsB[8] = {9,13,21,37,69,133,261,517};
    const unsigned FULL = 0xffffffffu;
    {
        float4 vb[5];
#pragma unroll
        for (int j = 0; j < 5; ++j) {
            int k = l - offsB[j]; k = k >= 0 ? k : 0;
            vb[j] = vbase[k * rs4];
        }
#pragma unroll
        for (int j = 0; j < 5; ++j) {
            const float wj = __shfl_sync(FULL, w, 8 + j, 16);
            acc.x = fmaf(wj, vb[j].x, acc.x);
            acc.y = fmaf(wj, vb[j].y, acc.y);
            acc.z = fmaf(wj, vb[j].z, acc.z);
            acc.w = fmaf(wj, vb[j].w, acc.w);
        }
    }
    {
        float4 vb[4];
#pragma unroll
        for (int j = 0; j < 3; ++j) {
            int k = l - offsB[5 + j]; k = k >= 0 ? k : 0;
            vb[j] = vbase[k * rs4];
        }
        { int k = l - 1029; k = k >= 0 ? k : 0; vb[3] = vbase[k * rs4]; }
#pragma unroll
        for (int j = 0; j < 3; ++j) {
            const float wj = __shfl_sync(FULL, w, 13 + j, 16);
            acc.x = fmaf(wj, vb[j].x, acc.x);
            acc.y = fmaf(wj, vb[j].y, acc.y);
            acc.z = fmaf(wj, vb[j].z, acc.z);
            acc.w = fmaf(wj, vb[j].w, acc.w);
        }
        acc.x = fmaf(w16, vb[3].x, acc.x);
        acc.y = fmaf(w16, vb[3].y, acc.y);
        acc.z = fmaf(w16, vb[3].z, acc.z);
        acc.w = fmaf(w16, vb[3].w, acc.w);
    }
}

__global__ __launch_bounds__(256, 4) void sparse_attn_kernel(
    const float* __restrict__ Q,
    const float* __restrict__ Kp,
    const float* __restrict__ Vp,
    float*       __restrict__ O)
{
    const unsigned FULL = 0xffffffffu;

    const int warp   = threadIdx.x >> 5;
    const int lane   = threadIdx.x & 31;
    const int lane16 = lane & 15;
    const int sub    = lane >> 4;                      // half id

    const int g0 = (blockIdx.x * 8 + warp) * 4;        // first of 4 queries (4-aligned)
    const int l0 = g0 & (Lq - 1);
    const int bh = g0 >> 11;
    const int h  = bh & (Hh - 1);
    const int b  = bh >> 3;

    const int lA = l0 + 2 * sub;                       // this half's first query
    const int lB = lA + 1;                             // and its neighbor

    const int rowstride = Hh * Ee;                     // 512 floats
    const int rs4       = rowstride / 4;
    const int base_bh   = b * Lq * rowstride + h * Ee;

    const float4* kbase = reinterpret_cast<const float4*>(Kp + base_bh) + lane16;
    const float4* vbase = reinterpret_cast<const float4*>(Vp + base_bh) + lane16;
    const float4* qbase = reinterpret_cast<const float4*>(Q + base_bh) + lane16;

    const float4 qA = qbase[lA * rs4];
    const float4 qB = qbase[lB * rs4];

    // ---- K window: 9-row union lB-i (i=0..8) shared by both queries ----
    float pA[8], pB[8];
    {
        float4 kw[5];
#pragma unroll
        for (int i = 0; i < 5; ++i) {
            int r = lB - i; r = r >= 0 ? r : 0;
            kw[i] = kbase[r * rs4];
        }
#pragma unroll
        for (int i = 0; i < 5; ++i) pB[i] = dot4(qB, kw[i]);
#pragma unroll
        for (int i = 1; i < 5; ++i) pA[i - 1] = dot4(qA, kw[i]);

        float4 kw2[4];
#pragma unroll
        for (int i = 0; i < 4; ++i) {
            int r = lB - (5 + i); r = r >= 0 ? r : 0;
            kw2[i] = kbase[r * rs4];
        }
#pragma unroll
        for (int i = 0; i < 3; ++i) pB[5 + i] = dot4(qB, kw2[i]);
#pragma unroll
        for (int i = 0; i < 4; ++i) pA[4 + i] = dot4(qA, kw2[i]);
    }
    const float aB = tree8(pB, lane16);
    const float aA = tree8(pA, lane16);

    // ---- K log phases (per query) ----
    float bA, s16A, bB, s16B;
    klog(kbase, rs4, lA, qA, lane16, bA, s16A);
    klog(kbase, rs4, lB, qB, lane16, bB, s16B);

    // ---- merge halves: lane j (0..15) ends with full score j ----
    const bool hi = lane16 & 8;
    float scA, scB;
    {
        const float send = hi ? aA : bA;
        const float r    = __shfl_xor_sync(FULL, send, 8);
        scA = (hi ? bA : aA) + r;
    }
    {
        const float send = hi ? aB : bB;
        const float r    = __shfl_xor_sync(FULL, send, 8);
        scB = (hi ? bB : aB) + r;
    }

    // ---- lane-parallel softmax, no max-subtraction (|s| <~ 6, fp32-safe) ----
    int my_off;
    {
        const int lo[16] = {0,1,2,3,4,5,6,7,9,13,21,37,69,133,261,517};
        my_off = lo[lane16];
    }
    float wA = (lA >= my_off) ? __expf(scA * 0.125f) : 0.f;
    float wB = (lB >= my_off) ? __expf(scB * 0.125f) : 0.f;
    const float w16A = (lA >= 1029) ? __expf(s16A * 0.125f) : 0.f;
    const float w16B = (lB >= 1029) ? __expf(s16B * 0.125f) : 0.f;

    float denA = wA, denB = wB;
#pragma unroll
    for (int m = 8; m; m >>= 1) {
        denA += __shfl_xor_sync(FULL, denA, m);
        denB += __shfl_xor_sync(FULL, denB, m);
    }
    denA += w16A;
    denB += w16B;
    const float invA = __fdividef(1.f, denA);
    const float invB = __fdividef(1.f, denB);

    // ---- V window: shared 9-row union feeds both accumulators ----
    float4 accA = make_float4(0.f, 0.f, 0.f, 0.f);
    float4 accB = make_float4(0.f, 0.f, 0.f, 0.f);
    {
        float4 vw[5];
#pragma unroll
        for (int i = 0; i < 5; ++i) {
            int r = lB - i; r = r >= 0 ? r : 0;
            vw[i] = vbase[r * rs4];
        }
#pragma unroll
        for (int i = 0; i < 5; ++i) {
            const float wj = __shfl_sync(FULL, wB, i, 16);
            accB.x = fmaf(wj, vw[i].x, accB.x);
            accB.y = fmaf(wj, vw[i].y, accB.y);
            accB.z = fmaf(wj, vw[i].z, accB.z);
            accB.w = fmaf(wj, vw[i].w, accB.w);
        }
#pragma unroll
        for (int i = 1; i < 5; ++i) {
            const float wj = __shfl_sync(FULL, wA, i - 1, 16);
            accA.x = fmaf(wj, vw[i].x, accA.x);
            accA.y = fmaf(wj, vw[i].y, accA.y);
            accA.z = fmaf(wj, vw[i].z, accA.z);
            accA.w = fmaf(wj, vw[i].w, accA.w);
        }
        float4 vw2[4];
#pragma unroll
        for (int i = 0; i < 4; ++i) {
            int r = lB - (5 + i); r = r >= 0 ? r : 0;
            vw2[i] = vbase[r * rs4];
        }
#pragma unroll
        for (int i = 0; i < 3; ++i) {
            const float wj = __shfl_sync(FULL, wB, 5 + i, 16);
            accB.x = fmaf(wj, vw2[i].x, accB.x);
            accB.y = fmaf(wj, vw2[i].y, accB.y);
            accB.z = fmaf(wj, vw2[i].z, accB.z);
            accB.w = fmaf(wj, vw2[i].w, accB.w);
        }
#pragma unroll
        for (int i = 0; i < 4; ++i) {
            const float wj = __shfl_sync(FULL, wA, 4 + i, 16);
            accA.x = fmaf(wj, vw2[i].x, accA.x);
            accA.y = fmaf(wj, vw2[i].y, accA.y);
            accA.z = fmaf(wj, vw2[i].z, accA.z);
            accA.w = fmaf(wj, vw2[i].w, accA.w);
        }
    }
    // ---- V log phases (per query) ----
    vlog(vbase, rs4, lA, wA, w16A, accA);
    vlog(vbase, rs4, lB, wB, w16B, accB);

    // ---- scale and store ----
    float4 oA, oB;
    oA.x = accA.x * invA; oA.y = accA.y * invA; oA.z = accA.z * invA; oA.w = accA.w * invA;
    oB.x = accB.x * invB; oB.y = accB.y * invB; oB.z = accB.z * invB; oB.w = accB.w * invB;

    float4* obase = reinterpret_cast<float4*>(O + base_bh) + lane16;
    obase[lA * rs4] = oA;
    obase[lB * rs4] = oB;
}

extern "C" void kernel_launch(void* const* d_in, const int* in_sizes, int n_in,
                              void* d_out, int out_size)
{
    const float* Q = (const float*)d_in[0];
    const float* K = (const float*)d_in[1];
    const float* V = (const float*)d_in[2];
    float*       O = (float*)d_out;

    // 65536 queries, 4 per warp, 8 warps per block -> 2048 blocks
    dim3 grid(2048);
    dim3 block(256);
    sparse_attn_kernel<<<grid, block>>>(Q, K, V, O);
}